// round 9
// baseline (speedup 1.0000x reference)
#include <cuda_runtime.h>
#include <cstdint>

// Depthwise causal FIR conv1d, K=31, fp32.
// x: (8, 4096, 2048) channel-last.  w: (2048, 31).  y like x.
//
// Round-9: R8 (register window + pinned smem taps) with a 128-reg cap.
//  - thread = channel pair (float2), TT=128 outputs, CHUNK=8, full unroll
//  - 38-slot circular register window (static mod-38), direct LDG.64 prefetch
//  - taps: smem ws[31][64], volatile ld.shared.v2.f32 into a 3-slot rotating
//    buffer (3-tap lead) -> ptxas cannot hoist (R7's spill mechanism removed)
//  - __launch_bounds__(64, 8): 128-reg cap, demand ~110 -> no spill,
//    8 blocks = 16 warps/SM (4/SMSP) to fill the chunk-boundary latency gaps

#define BB 8
#define LL 4096
#define CPAIR 1024
#define KK 31
#define CHUNK 8
#define TT 128
#define NCHUNK 16
#define WBUF 38
#define THREADS 64

__device__ __forceinline__ float2 ffma2(float2 a, float2 b, float2 c) {
    float2 d;
    asm("fma.rn.f32x2 %0, %1, %2, %3;"
        : "=l"(*reinterpret_cast<unsigned long long*>(&d))
        : "l"(*reinterpret_cast<const unsigned long long*>(&a)),
          "l"(*reinterpret_cast<const unsigned long long*>(&b)),
          "l"(*reinterpret_cast<const unsigned long long*>(&c)));
    return d;
}

// Pinned LDS.64: volatile keeps ptxas from hoisting/batching weight loads.
__device__ __forceinline__ float2 lds_wt(uint32_t addr) {
    float2 v;
    asm volatile("ld.shared.v2.f32 {%0, %1}, [%2];"
                 : "=f"(v.x), "=f"(v.y) : "r"(addr));
    return v;
}

__global__ __launch_bounds__(THREADS, 8)
void _DepthwiseFIRConv1d_kernel(const float* __restrict__ x,
                                const float* __restrict__ w,
                                float* __restrict__ y) {
    __shared__ float2 ws[KK][THREADS];                   // 15872 B

    const int tid = threadIdx.x;
    const int cpi = blockIdx.x * THREADS + tid;          // channel pair 0..1023
    const int l0  = blockIdx.y * TT;
    const int b   = blockIdx.z;

    const float2* xb = reinterpret_cast<const float2*>(x) + (size_t)b * LL * CPAIR + cpi;
    float2*       yb = reinterpret_cast<float2*>(y) + ((size_t)b * LL + l0) * CPAIR + cpi;
    const int base = l0 - (KK - 1);

    // Stage taps into smem: ws[t][tid] = (w[2cp][t], w[2cp+1][t]).
    {
        const float* w0 = w + (2 * cpi) * KK;
#pragma unroll
        for (int t = 0; t < KK; t++)
            ws[t][tid] = make_float2(__ldg(w0 + t), __ldg(w0 + KK + t));
    }
    __syncthreads();

    const uint32_t ws0 = (uint32_t)__cvta_generic_to_shared(&ws[0][tid]);

    // Initial window: offsets 0..37. Predicate only bites when l0==0.
    float2 buf[WBUF];
#pragma unroll
    for (int i = 0; i < WBUF; i++) {
        const int l = base + i;
        buf[i] = (l >= 0) ? xb[(size_t)l * CPAIR] : make_float2(0.0f, 0.0f);
    }

#pragma unroll
    for (int c = 0; c < NCHUNK; c++) {
        float2 acc[CHUNK];
#pragma unroll
        for (int j = 0; j < CHUNK; j++) acc[j] = make_float2(0.0f, 0.0f);

        // 3-slot rotating weight buffer, 3-tap lead (>= LDS latency).
        float2 wr[3];
        wr[0] = lds_wt(ws0 + 0 * (THREADS * 8));
        wr[1] = lds_wt(ws0 + 1 * (THREADS * 8));
        wr[2] = lds_wt(ws0 + 2 * (THREADS * 8));

#pragma unroll
        for (int t = 0; t < KK; t++) {
            const float2 wt = wr[t % 3];
#pragma unroll
            for (int j = 0; j < CHUNK; j++)
                acc[j] = ffma2(wt, buf[(CHUNK * c + j + t) % WBUF], acc[j]);
            if (t + 3 < KK)
                wr[t % 3] = lds_wt(ws0 + (uint32_t)(t + 3) * (THREADS * 8));
        }

#pragma unroll
        for (int j = 0; j < CHUNK; j++)
            yb[(size_t)(CHUNK * c + j) * CPAIR] = acc[j];

        // Prefetch offsets 8c+38 .. 8c+45 into the slots chunk c retired.
        // l = l0 + 8c + 8 + i: always in [0, LL).
        if (c < NCHUNK - 1) {
#pragma unroll
            for (int i = 0; i < CHUNK; i++) {
                const int off = CHUNK * c + WBUF + i;
                buf[(CHUNK * c + i) % WBUF] = xb[(size_t)(base + off) * CPAIR];
            }
        }
    }
}

extern "C" void kernel_launch(void* const* d_in, const int* in_sizes, int n_in,
                              void* d_out, int out_size) {
    const float* x = (const float*)d_in[0];   // (8, 4096, 16, 128)
    const float* w = (const float*)d_in[1];   // (16, 128, 31)
    float* yv = (float*)d_out;

    dim3 grid(CPAIR / THREADS, LL / TT, BB);  // (16, 32, 8) = 4096 blocks
    _DepthwiseFIRConv1d_kernel<<<grid, THREADS>>>(x, w, yv);
}

// round 10
// speedup vs baseline: 2.2384x; 2.2384x over previous
#include <cuda_runtime.h>
#include <cstdint>

// Depthwise causal FIR conv1d, K=31, fp32.
// x: (8, 4096, 2048) channel-last.  w: (2048, 31).  y like x.
//
// Round-10: tap-split kernel. Lanes L and L^16 of a warp handle the SAME
// channel pair; half 0 does taps 0-14, half 1 taps 15-30 (uniform 16-tap loop,
// half 0's 16th tap is zero). Partials combine via shfl_xor(16); each half
// stores 4 of the 8 chunk outputs.
//  - per-thread window: 23 float2 slots (46 regs) vs 38 (76) before
//  - taps: pinned smem (asm-volatile LDS.64, 3-slot rotation) -> no hoist
//  - NO launch_bounds cap (caps proved to spill in R7/R9)

#define BB 8
#define LL 4096
#define CPAIR 1024
#define KK 31
#define TAPS 16          // taps per half (half0: 15 real + 1 zero)
#define CHUNK 8
#define TT 128
#define NCHUNK 16
#define WBUF 23          // 8 + 15 halo
#define THREADS 64       // 2 warps; warp = 16 channel pairs x 2 tap-halves

__device__ __forceinline__ float2 ffma2(float2 a, float2 b, float2 c) {
    float2 d;
    asm("fma.rn.f32x2 %0, %1, %2, %3;"
        : "=l"(*reinterpret_cast<unsigned long long*>(&d))
        : "l"(*reinterpret_cast<const unsigned long long*>(&a)),
          "l"(*reinterpret_cast<const unsigned long long*>(&b)),
          "l"(*reinterpret_cast<const unsigned long long*>(&c)));
    return d;
}

// Pinned LDS.64 (ptxas cannot hoist/batch).
__device__ __forceinline__ float2 lds_wt(uint32_t addr) {
    float2 v;
    asm volatile("ld.shared.v2.f32 {%0, %1}, [%2];"
                 : "=f"(v.x), "=f"(v.y) : "r"(addr));
    return v;
}

__global__ __launch_bounds__(THREADS)
void _DepthwiseFIRConv1d_kernel(const float* __restrict__ x,
                                const float* __restrict__ w,
                                float* __restrict__ y) {
    __shared__ float2 ws[TAPS][THREADS];                 // 8 KB

    const int tid  = threadIdx.x;
    const int half = (tid >> 4) & 1;                     // 0: taps 0-14, 1: taps 15-30
    const int cpi  = blockIdx.x * 32 + (tid >> 5) * 16 + (tid & 15);
    const int l0   = blockIdx.y * TT;
    const int b    = blockIdx.z;

    const int tap_base = half * 15;
    const int base = l0 - (KK - 1) + tap_base;           // x offset of window slot 0

    const float2* xb = reinterpret_cast<const float2*>(x) + (size_t)b * LL * CPAIR + cpi;
    float2*       yb = reinterpret_cast<float2*>(y) + ((size_t)b * LL + l0) * CPAIR + cpi;

    // Stage this thread's 16 taps into smem (half0's 16th tap = 0).
    {
        const float* w0 = w + (2 * cpi) * KK + tap_base;
#pragma unroll
        for (int t = 0; t < TAPS; t++) {
            const bool valid = half || (t < 15);
            ws[t][tid] = valid ? make_float2(__ldg(w0 + t), __ldg(w0 + KK + t))
                               : make_float2(0.0f, 0.0f);
        }
    }
    __syncthreads();

    const uint32_t ws0 = (uint32_t)__cvta_generic_to_shared(&ws[0][tid]);

    // Initial window: offsets 0..22 (chunk 0 span). l < 0 only near l0==0.
    float2 buf[WBUF];
#pragma unroll
    for (int i = 0; i < WBUF; i++) {
        const int l = base + i;
        buf[i] = (l >= 0) ? xb[(size_t)l * CPAIR] : make_float2(0.0f, 0.0f);
    }

#pragma unroll
    for (int c = 0; c < NCHUNK; c++) {
        float2 acc[CHUNK];
#pragma unroll
        for (int j = 0; j < CHUNK; j++) acc[j] = make_float2(0.0f, 0.0f);

        float2 wr[3];
        wr[0] = lds_wt(ws0 + 0 * (THREADS * 8));
        wr[1] = lds_wt(ws0 + 1 * (THREADS * 8));
        wr[2] = lds_wt(ws0 + 2 * (THREADS * 8));

#pragma unroll
        for (int t = 0; t < TAPS; t++) {
            const float2 wt = wr[t % 3];
#pragma unroll
            for (int j = 0; j < CHUNK; j++)
                acc[j] = ffma2(wt, buf[(CHUNK * c + j + t) % WBUF], acc[j]);
            if (t + 3 < TAPS)
                wr[t % 3] = lds_wt(ws0 + (uint32_t)(t + 3) * (THREADS * 8));
        }

        // Combine halves: lane L <-> L^16 hold the two tap-halves of the
        // same channel pair. Butterfly-sum all 8 accs, each half stores 4.
        float2 sum[CHUNK];
#pragma unroll
        for (int j = 0; j < CHUNK; j++) {
            const float ox = __shfl_xor_sync(0xFFFFFFFFu, acc[j].x, 16);
            const float oy = __shfl_xor_sync(0xFFFFFFFFu, acc[j].y, 16);
            sum[j] = make_float2(acc[j].x + ox, acc[j].y + oy);
        }

        if (half == 0) {
            yb[(size_t)(CHUNK * c + 0) * CPAIR] = sum[0];
            yb[(size_t)(CHUNK * c + 1) * CPAIR] = sum[1];
            yb[(size_t)(CHUNK * c + 2) * CPAIR] = sum[2];
            yb[(size_t)(CHUNK * c + 3) * CPAIR] = sum[3];
        } else {
            yb[(size_t)(CHUNK * c + 4) * CPAIR] = sum[4];
            yb[(size_t)(CHUNK * c + 5) * CPAIR] = sum[5];
            yb[(size_t)(CHUNK * c + 6) * CPAIR] = sum[6];
            yb[(size_t)(CHUNK * c + 7) * CPAIR] = sum[7];
        }

        // Prefetch offsets 8c+23 .. 8c+30 into the slots chunk c retired.
        // l = base+8c+23+i: can be <0 only for l0==0/half0 (predicated);
        // max l = l0+127 (half1, c=14) -> in range.
        if (c < NCHUNK - 1) {
#pragma unroll
            for (int i = 0; i < CHUNK; i++) {
                const int off = CHUNK * c + WBUF + i;
                const int l = base + off;
                buf[(CHUNK * c + i) % WBUF] =
                    (l >= 0) ? xb[(size_t)l * CPAIR] : make_float2(0.0f, 0.0f);
            }
        }
    }
}

extern "C" void kernel_launch(void* const* d_in, const int* in_sizes, int n_in,
                              void* d_out, int out_size) {
    const float* x = (const float*)d_in[0];   // (8, 4096, 16, 128)
    const float* w = (const float*)d_in[1];   // (16, 128, 31)
    float* yv = (float*)d_out;

    dim3 grid(CPAIR / 32, LL / TT, BB);       // (32, 32, 8) = 8192 blocks
    _DepthwiseFIRConv1d_kernel<<<grid, THREADS>>>(x, w, yv);
}